// round 13
// baseline (speedup 1.0000x reference)
#include <cuda_runtime.h>
#include <cuda_bf16.h>
#include <cstdint>

#define NN 20000
#define EE 1280000
#define CC 256
#define STR 160   // bucket stride (max degree ~100 at 12 sigma)

// ---------------- device scratch (no allocations allowed) ----------------
__device__ __align__(16) uint32_t g_xwh[(size_t)NN * 128]; // x@W1_l^T bf16x2
__device__ __align__(16) float    g_xr[(size_t)NN * CC];   // x@W1_r^T + b1
__device__ __align__(16) uint32_t g_xh[(size_t)NN * 128];  // x hi split bf16x2
__device__ __align__(16) uint32_t g_xl[(size_t)NN * 128];  // x lo split
__device__ __align__(16) uint32_t g_wh[512 * 128];         // W hi split
__device__ __align__(16) uint32_t g_wl[512 * 128];         // W lo split
__device__ int   g_cnt[NN];
__device__ __align__(16) int g_bucket[(size_t)NN * STR];
__device__ float g_s[NN];
__device__ float g_t[NN];
__device__ float g_part[2560];
__device__ int   g_done;

__device__ __forceinline__ int clampN(int v) { return min(max(v, 0), NN - 1); }

__device__ __forceinline__ void bf16_split_pair(float a, float b, uint32_t& hi, uint32_t& lo) {
    __nv_bfloat16 ah = __float2bfloat16_rn(a);
    __nv_bfloat16 bh = __float2bfloat16_rn(b);
    __nv_bfloat16 al = __float2bfloat16_rn(a - __bfloat162float(ah));
    __nv_bfloat16 bl = __float2bfloat16_rn(b - __bfloat162float(bh));
    hi = ((uint32_t)__bfloat16_as_ushort(bh) << 16) | __bfloat16_as_ushort(ah);
    lo = ((uint32_t)__bfloat16_as_ushort(bl) << 16) | __bfloat16_as_ushort(al);
}
__device__ __forceinline__ uint32_t pack_bf16x2(float a, float b) {
    __nv_bfloat162 h = __floats2bfloat162_rn(a, b);
    return *(uint32_t*)&h;
}
__device__ __forceinline__ uint32_t hadd2u(uint32_t a, uint32_t b) {
    __nv_bfloat162 r = __hadd2(*(__nv_bfloat162*)&a, *(__nv_bfloat162*)&b);
    return *(uint32_t*)&r;
}

// ====== prep: zero cnt | x-split | W-split ===============================
#define ZB 79
#define XC_B 5000
#define WC_B 128

__global__ __launch_bounds__(256) void prep_kernel(
    const float* __restrict__ x,
    const float* __restrict__ Wl, const float* __restrict__ Wr)
{
    int b = blockIdx.x;
    int tid = threadIdx.x;
    if (b < ZB) {
        int t = b * 256 + tid;
        if (t < NN) g_cnt[t] = 0;
        if (b == 0 && tid == 0) g_done = 0;
    } else if (b < ZB + XC_B) {
        int e = ((b - ZB) * 256 + tid) * 4;
        float4 v = *(const float4*)(x + e);
        uint32_t h0, l0, h1, l1;
        bf16_split_pair(v.x, v.y, h0, l0);
        bf16_split_pair(v.z, v.w, h1, l1);
        int row = e >> 8, kk = e & 255;
        size_t o = (size_t)row * 128 + (kk >> 1);
        *(uint2*)(g_xh + o) = make_uint2(h0, h1);
        *(uint2*)(g_xl + o) = make_uint2(l0, l1);
    } else {
        int e = ((b - ZB - XC_B) * 256 + tid) * 4;  // over 512*256
        int row = e >> 8, kk = e & 255;
        const float* W = (row < 256) ? (Wl + (size_t)row * CC + kk)
                                     : (Wr + (size_t)(row - 256) * CC + kk);
        float4 v = *(const float4*)W;
        uint32_t h0, l0, h1, l1;
        bf16_split_pair(v.x, v.y, h0, l0);
        bf16_split_pair(v.z, v.w, h1, l1);
        size_t o = (size_t)row * 128 + (kk >> 1);
        *(uint2*)(g_wh + o) = make_uint2(h0, h1);
        *(uint2*)(g_wl + o) = make_uint2(l0, l1);
    }
}

// ========== fused: interleaved scatter + double-buffered bf16 GEMM =======
// bid < 1250: odd -> scatter (bid>>1), even -> GEMM (bid>>1)
// bid >= 1250: GEMM (bid - 625)
// GEMM: xw blocks 2-term (Ah*Bh + Al*Bh), xr blocks 3-term (+ Ah*Bl).
#define SCAT_B 625
#define GEMM_BX 157

#define KC 32
#define KS 2
#define A_FRAG_U32 (8 * KS * 32 * 4)
#define B_FRAG_U32 (16 * KS * 32 * 2)

struct SmemGemm {
    uint32_t AH[A_FRAG_U32];
    uint32_t AL[A_FRAG_U32];
    uint32_t BH[B_FRAG_U32];
    uint32_t BL[B_FRAG_U32];
};
#define SMEM_DYN (2 * sizeof(SmemGemm))   // 64 KB, 2 stages

#define MMA_BF16(d, a, b) \
    asm volatile("mma.sync.aligned.m16n8k16.row.col.f32.bf16.bf16.f32 " \
                 "{%0,%1,%2,%3}, {%4,%5,%6,%7}, {%8,%9}, {%0,%1,%2,%3};" \
                 : "+f"((d)[0]), "+f"((d)[1]), "+f"((d)[2]), "+f"((d)[3]) \
                 : "r"((a).x), "r"((a).y), "r"((a).z), "r"((a).w), \
                   "r"((b).x), "r"((b).y))

__global__ __launch_bounds__(256, 2) void gemm_scat_kernel(
    const int* __restrict__ ei, const float* __restrict__ b1)
{
    extern __shared__ uint32_t dyn_smem[];
    SmemGemm* bufs = (SmemGemm*)dyn_smem;
    const int bid = blockIdx.x;
    const int tid = threadIdx.x;

    if (bid < 2 * SCAT_B && (bid & 1)) {
        // ---------------- scatter path ----------------
        int e8 = ((bid >> 1) * 256 + tid) * 8;
        #pragma unroll
        for (int h = 0; h < 2; h++) {
            int4 s = *(const int4*)(ei + e8 + h * 4);
            int4 d = *(const int4*)(ei + EE + e8 + h * 4);
            int d0 = clampN(d.x), d1 = clampN(d.y), d2 = clampN(d.z), d3 = clampN(d.w);
            int p0 = atomicAdd(&g_cnt[d0], 1);
            int p1 = atomicAdd(&g_cnt[d1], 1);
            int p2 = atomicAdd(&g_cnt[d2], 1);
            int p3 = atomicAdd(&g_cnt[d3], 1);
            if (p0 < STR) g_bucket[(size_t)d0 * STR + p0] = clampN(s.x);
            if (p1 < STR) g_bucket[(size_t)d1 * STR + p1] = clampN(s.y);
            if (p2 < STR) g_bucket[(size_t)d2 * STR + p2] = clampN(s.z);
            if (p3 < STR) g_bucket[(size_t)d3 * STR + p3] = clampN(s.w);
        }
        return;
    }

    // ---------------- GEMM path ----------------
    const int g = (bid < 2 * SCAT_B) ? (bid >> 1) : (bid - SCAT_B);
    const int m0 = (g % GEMM_BX) * 128;
    const int j0 = (g / GEMM_BX) * 128;
    const bool to_xw = (j0 < 256);

    const int wid = tid >> 5;
    const int lane = tid & 31;
    const int wr = wid >> 1;
    const int wc = wid & 1;

    const int prow = tid >> 1;
    const int phalf = tid & 1;
    const int rr = prow & 15;
    const int msub = prow >> 4;
    const int nsub = prow >> 3;
    const int nn = prow & 7;

    const int garow = m0 + prow;
    const bool avalid = (garow < NN);
    const uint4* xh4 = (const uint4*)(g_xh + (size_t)min(garow, NN - 1) * 128);
    const uint4* xl4 = (const uint4*)(g_xl + (size_t)min(garow, NN - 1) * 128);
    const uint4* wh4 = (const uint4*)(g_wh + (size_t)(j0 + prow) * 128);
    const uint4* wl4 = (const uint4*)(g_wl + (size_t)(j0 + prow) * 128);

    uint4 rah0, rah1, ral0, ral1, rbh0, rbh1, rbl0, rbl1;

    auto load_regs = [&](int kc) {
        int u = kc * 4 + phalf * 2;
        rah0 = xh4[u]; rah1 = xh4[u + 1];
        ral0 = xl4[u]; ral1 = xl4[u + 1];
        if (!avalid) { rah0 = rah1 = ral0 = ral1 = make_uint4(0, 0, 0, 0); }
        rbh0 = wh4[u]; rbh1 = wh4[u + 1];
        if (!to_xw) { rbl0 = wl4[u]; rbl1 = wl4[u + 1]; }
    };
    auto store_smem = [&](SmemGemm* S) {
        #pragma unroll
        for (int q = 0; q < 8; q++) {
            uint32_t ah = (q < 4) ? ((const uint32_t*)&rah0)[q] : ((const uint32_t*)&rah1)[q - 4];
            uint32_t al = (q < 4) ? ((const uint32_t*)&ral0)[q] : ((const uint32_t*)&ral1)[q - 4];
            uint32_t bh = (q < 4) ? ((const uint32_t*)&rbh0)[q] : ((const uint32_t*)&rbh1)[q - 4];
            int alane = (rr & 7) * 4 + (q & 3);
            int aslot = (rr >> 3) + ((q >> 2) << 1);
            int aoff = (((msub * KS + phalf) * 32 + alane) << 2) + aslot;
            S->AH[aoff] = ah; S->AL[aoff] = al;
            int blane = nn * 4 + (q & 3);
            int bslot = q >> 2;
            int boff = (((nsub * KS + phalf) * 32 + blane) << 1) + bslot;
            S->BH[boff] = bh;
        }
        if (!to_xw) {
            #pragma unroll
            for (int q = 0; q < 8; q++) {
                uint32_t bl = (q < 4) ? ((const uint32_t*)&rbl0)[q] : ((const uint32_t*)&rbl1)[q - 4];
                int blane = nn * 4 + (q & 3);
                int bslot = q >> 2;
                int boff = (((nsub * KS + phalf) * 32 + blane) << 1) + bslot;
                S->BL[boff] = bl;
            }
        }
    };

    float acc[2][8][4];
    #pragma unroll
    for (int mi = 0; mi < 2; mi++)
        #pragma unroll
        for (int ni = 0; ni < 8; ni++)
            #pragma unroll
            for (int q = 0; q < 4; q++) acc[mi][ni][q] = 0.f;

    load_regs(0);
    store_smem(&bufs[0]);
    __syncthreads();

    for (int kc = 0; kc < CC / KC; kc++) {
        if (kc + 1 < CC / KC) load_regs(kc + 1);    // prefetch overlaps MMA
        SmemGemm* cur = &bufs[kc & 1];
        #pragma unroll
        for (int ks = 0; ks < KS; ks++) {
            uint4 Ah[2], Al[2];
            #pragma unroll
            for (int mi = 0; mi < 2; mi++) {
                int ms = wr * 2 + mi;
                int off = ((ms * KS + ks) * 32 + lane) << 2;
                Ah[mi] = *(const uint4*)&cur->AH[off];
                Al[mi] = *(const uint4*)&cur->AL[off];
            }
            #pragma unroll
            for (int ni = 0; ni < 8; ni++) {
                int ns = wc * 8 + ni;
                int boff = ((ns * KS + ks) * 32 + lane) << 1;
                uint2 Bh = *(const uint2*)&cur->BH[boff];
                #pragma unroll
                for (int mi = 0; mi < 2; mi++) {
                    MMA_BF16(acc[mi][ni], Ah[mi], Bh);
                    MMA_BF16(acc[mi][ni], Al[mi], Bh);
                }
                if (!to_xw) {
                    uint2 Bl = *(const uint2*)&cur->BL[boff];
                    #pragma unroll
                    for (int mi = 0; mi < 2; mi++)
                        MMA_BF16(acc[mi][ni], Ah[mi], Bl);
                }
            }
        }
        if (kc + 1 < CC / KC) store_smem(&bufs[(kc + 1) & 1]);
        __syncthreads();
    }

    #pragma unroll
    for (int mi = 0; mi < 2; mi++) {
        int r0 = m0 + wr * 32 + mi * 16 + (lane >> 2);
        #pragma unroll
        for (int ni = 0; ni < 8; ni++) {
            int col = j0 + wc * 64 + ni * 8 + (lane & 3) * 2;
            if (to_xw) {
                if (r0 < NN)
                    g_xwh[(size_t)r0 * 128 + (col >> 1)] = pack_bf16x2(acc[mi][ni][0], acc[mi][ni][1]);
                if (r0 + 8 < NN)
                    g_xwh[(size_t)(r0 + 8) * 128 + (col >> 1)] = pack_bf16x2(acc[mi][ni][2], acc[mi][ni][3]);
            } else {
                int jj = col - 256;
                float2 bv = *(const float2*)(b1 + jj);
                if (r0 < NN)
                    *(float2*)(g_xr + (size_t)r0 * CC + jj) =
                        make_float2(acc[mi][ni][0] + bv.x, acc[mi][ni][1] + bv.y);
                if (r0 + 8 < NN)
                    *(float2*)(g_xr + (size_t)(r0 + 8) * CC + jj) =
                        make_float2(acc[mi][ni][2] + bv.x, acc[mi][ni][3] + bv.y);
            }
        }
    }
}

// ---- fused: bf16 bucket gather (depth-2 HADD2 tree) + epilogue + proj ---
__device__ __forceinline__ void accum8(float* a, uint4 q) {
    a[0] += __uint_as_float(q.x << 16);
    a[1] += __uint_as_float(q.x & 0xFFFF0000u);
    a[2] += __uint_as_float(q.y << 16);
    a[3] += __uint_as_float(q.y & 0xFFFF0000u);
    a[4] += __uint_as_float(q.z << 16);
    a[5] += __uint_as_float(q.z & 0xFFFF0000u);
    a[6] += __uint_as_float(q.w << 16);
    a[7] += __uint_as_float(q.w & 0xFFFF0000u);
}
__device__ __forceinline__ uint4 hadd2u4(uint4 a, uint4 b) {
    return make_uint4(hadd2u(a.x, b.x), hadd2u(a.y, b.y),
                      hadd2u(a.z, b.z), hadd2u(a.w, b.w));
}

__global__ __launch_bounds__(128) void agg_st_kernel(const float* __restrict__ W2l,
                                                     const float* __restrict__ W2r)
{
    int n = (int)((blockIdx.x * 128 + threadIdx.x) >> 5);
    int lane = threadIdx.x & 31;
    if (n >= NN) return;
    const int* lst = g_bucket + (size_t)n * STR;
    int cnt = g_cnt[n];
    int m = min(cnt, STR);

    const uint4* base = (const uint4*)g_xwh;   // row = 32 uint4
    float a[8] = {};

    int i = 0;
    for (; i + 4 <= m; i += 4) {
        int4 s4 = *(const int4*)(lst + i);
        uint4 q0 = base[(size_t)s4.x * 32 + lane];
        uint4 q1 = base[(size_t)s4.y * 32 + lane];
        uint4 q2 = base[(size_t)s4.z * 32 + lane];
        uint4 q3 = base[(size_t)s4.w * 32 + lane];
        accum8(a, hadd2u4(hadd2u4(q0, q1), hadd2u4(q2, q3)));   // depth-2 bf16 tree
    }
    if (i + 2 <= m) {
        uint4 q0 = base[(size_t)lst[i] * 32 + lane];
        uint4 q1 = base[(size_t)lst[i + 1] * 32 + lane];
        accum8(a, hadd2u4(q0, q1));
        i += 2;
    }
    if (i < m) {
        accum8(a, base[(size_t)lst[i] * 32 + lane]);
    }

    float inv = 1.0f / fmaxf((float)cnt, 1.0f);
    float su = 0.f, tv = 0.f;
    {
        int c0 = lane * 8;
        float4 R = *(const float4*)(g_xr + (size_t)n * CC + c0);
        float4 U = __ldg((const float4*)(W2l + c0));
        float4 V = __ldg((const float4*)(W2r + c0));
        float h;
        h = fmaxf(fmaf(inv, a[0], R.x), 0.f); su = fmaf(h, U.x, su); tv = fmaf(h, V.x, tv);
        h = fmaxf(fmaf(inv, a[1], R.y), 0.f); su = fmaf(h, U.y, su); tv = fmaf(h, V.y, tv);
        h = fmaxf(fmaf(inv, a[2], R.z), 0.f); su = fmaf(h, U.z, su); tv = fmaf(h, V.z, tv);
        h = fmaxf(fmaf(inv, a[3], R.w), 0.f); su = fmaf(h, U.w, su); tv = fmaf(h, V.w, tv);
        R = *(const float4*)(g_xr + (size_t)n * CC + c0 + 4);
        U = __ldg((const float4*)(W2l + c0 + 4));
        V = __ldg((const float4*)(W2r + c0 + 4));
        h = fmaxf(fmaf(inv, a[4], R.x), 0.f); su = fmaf(h, U.x, su); tv = fmaf(h, V.x, tv);
        h = fmaxf(fmaf(inv, a[5], R.y), 0.f); su = fmaf(h, U.y, su); tv = fmaf(h, V.y, tv);
        h = fmaxf(fmaf(inv, a[6], R.z), 0.f); su = fmaf(h, U.z, su); tv = fmaf(h, V.z, tv);
        h = fmaxf(fmaf(inv, a[7], R.w), 0.f); su = fmaf(h, U.w, su); tv = fmaf(h, V.w, tv);
    }
    #pragma unroll
    for (int o = 16; o > 0; o >>= 1) {
        su += __shfl_down_sync(0xffffffffu, su, o);
        tv += __shfl_down_sync(0xffffffffu, tv, o);
    }
    if (lane == 0) { g_s[n] = su; g_t[n] = tv; }
}

// ---- fused: layer-2 gather + relu + fc dot + last-block final reduce ----
#define L2_B 2500

__global__ __launch_bounds__(256) void l2final_kernel(const float* __restrict__ fcw,
                                                      const float* __restrict__ b2,
                                                      const float* __restrict__ fcb,
                                                      float* __restrict__ out)
{
    __shared__ float ws[8];
    __shared__ int isLast;
    int tid = threadIdx.x;
    int wid = tid >> 5;
    int lane = tid & 31;
    int n = (int)((blockIdx.x * 256 + tid) >> 5);
    float local = 0.f;
    if (n < NN) {
        const int* lst = g_bucket + (size_t)n * STR;
        int cnt = g_cnt[n];
        int m = min(cnt, STR);
        float sum = 0.f;
        for (int i = lane; i < m; i += 32) sum += g_s[lst[i]];
        #pragma unroll
        for (int o = 16; o > 0; o >>= 1)
            sum += __shfl_down_sync(0xffffffffu, sum, o);
        if (lane == 0) {
            float inv = 1.0f / fmaxf((float)cnt, 1.0f);
            float h = fmaxf(fmaf(inv, sum, b2[0] + g_t[n]), 0.f);
            local = h * fcw[n];
        }
    }
    if (lane == 0) ws[wid] = local;
    __syncthreads();
    if (tid == 0) {
        float s = ws[0] + ws[1] + ws[2] + ws[3] + ws[4] + ws[5] + ws[6] + ws[7];
        g_part[blockIdx.x] = s;
        __threadfence();
        isLast = (atomicAdd(&g_done, 1) == L2_B - 1);
    }
    __syncthreads();
    if (isLast) {
        // deterministic final reduce by the single last block
        __shared__ float sdata[256];
        float v = 0.f;
        for (int i = tid; i < L2_B; i += 256) v += g_part[i];
        sdata[tid] = v;
        __syncthreads();
        for (int s = 128; s > 0; s >>= 1) {
            if (tid < s) sdata[tid] += sdata[tid + s];
            __syncthreads();
        }
        if (tid == 0) out[0] = sdata[0] + fcb[0];
    }
}

// ---------------- launch ----------------
extern "C" void kernel_launch(void* const* d_in, const int* in_sizes, int n_in,
                              void* d_out, int out_size) {
    const float* x    = (const float*)d_in[0];
    const int*   ei   = (const int*)d_in[1];     // int32 (JAX x64 disabled)
    const float* W1l  = (const float*)d_in[2];
    const float* b1   = (const float*)d_in[3];
    const float* W1r  = (const float*)d_in[4];
    const float* W2l  = (const float*)d_in[5];
    const float* b2   = (const float*)d_in[6];
    const float* W2r  = (const float*)d_in[7];
    const float* fcw  = (const float*)d_in[8];
    const float* fcb  = (const float*)d_in[9];
    float* out = (float*)d_out;

    static bool attr_set = false;
    if (!attr_set) {
        cudaFuncSetAttribute(gemm_scat_kernel,
                             cudaFuncAttributeMaxDynamicSharedMemorySize, (int)SMEM_DYN);
        attr_set = true;
    }

    prep_kernel<<<ZB + XC_B + WC_B, 256>>>(x, W1l, W1r);

    gemm_scat_kernel<<<2 * SCAT_B + 3, 256, SMEM_DYN>>>(ei, b1);

    agg_st_kernel<<<(NN * 32 + 127) / 128, 128>>>(W2l, W2r);

    l2final_kernel<<<L2_B, 256>>>(fcw, b2, fcb, out);
}

// round 14
// speedup vs baseline: 1.6256x; 1.6256x over previous
#include <cuda_runtime.h>
#include <cuda_bf16.h>
#include <cstdint>

#define NN 20000
#define EE 1280000
#define CC 256
#define STR 160   // bucket stride (max degree ~100 at 12 sigma)

// ---------------- device scratch (no allocations allowed) ----------------
__device__ __align__(16) uint32_t g_xwh[(size_t)NN * 128]; // x@W1_l^T bf16x2
__device__ __align__(16) float    g_xr[(size_t)NN * CC];   // x@W1_r^T + b1
__device__ __align__(16) uint32_t g_xh[(size_t)NN * 128];  // x hi split bf16x2
__device__ __align__(16) uint32_t g_xl[(size_t)NN * 128];  // x lo split
__device__ __align__(16) uint32_t g_wh[512 * 128];         // W hi split
__device__ __align__(16) uint32_t g_wl[512 * 128];         // W lo split
__device__ int   g_cnt[NN];
__device__ __align__(16) int g_bucket[(size_t)NN * STR];
__device__ float g_s[NN];
__device__ float g_t[NN];
__device__ float g_part[2560];

__device__ __forceinline__ int clampN(int v) { return min(max(v, 0), NN - 1); }

__device__ __forceinline__ void bf16_split_pair(float a, float b, uint32_t& hi, uint32_t& lo) {
    __nv_bfloat16 ah = __float2bfloat16_rn(a);
    __nv_bfloat16 bh = __float2bfloat16_rn(b);
    __nv_bfloat16 al = __float2bfloat16_rn(a - __bfloat162float(ah));
    __nv_bfloat16 bl = __float2bfloat16_rn(b - __bfloat162float(bh));
    hi = ((uint32_t)__bfloat16_as_ushort(bh) << 16) | __bfloat16_as_ushort(ah);
    lo = ((uint32_t)__bfloat16_as_ushort(bl) << 16) | __bfloat16_as_ushort(al);
}
__device__ __forceinline__ uint32_t pack_bf16x2(float a, float b) {
    __nv_bfloat162 h = __floats2bfloat162_rn(a, b);
    return *(uint32_t*)&h;
}
__device__ __forceinline__ uint32_t hadd2u(uint32_t a, uint32_t b) {
    __nv_bfloat162 r = __hadd2(*(__nv_bfloat162*)&a, *(__nv_bfloat162*)&b);
    return *(uint32_t*)&r;
}

// ====== prep: zero cnt | x-split | W-split ===============================
#define ZB 79
#define XC_B 5000
#define WC_B 128

__global__ __launch_bounds__(256) void prep_kernel(
    const float* __restrict__ x,
    const float* __restrict__ Wl, const float* __restrict__ Wr)
{
    int b = blockIdx.x;
    int tid = threadIdx.x;
    if (b < ZB) {
        int t = b * 256 + tid;
        if (t < NN) g_cnt[t] = 0;
    } else if (b < ZB + XC_B) {
        int e = ((b - ZB) * 256 + tid) * 4;
        float4 v = *(const float4*)(x + e);
        uint32_t h0, l0, h1, l1;
        bf16_split_pair(v.x, v.y, h0, l0);
        bf16_split_pair(v.z, v.w, h1, l1);
        int row = e >> 8, kk = e & 255;
        size_t o = (size_t)row * 128 + (kk >> 1);
        *(uint2*)(g_xh + o) = make_uint2(h0, h1);
        *(uint2*)(g_xl + o) = make_uint2(l0, l1);
    } else {
        int e = ((b - ZB - XC_B) * 256 + tid) * 4;  // over 512*256
        int row = e >> 8, kk = e & 255;
        const float* W = (row < 256) ? (Wl + (size_t)row * CC + kk)
                                     : (Wr + (size_t)(row - 256) * CC + kk);
        float4 v = *(const float4*)W;
        uint32_t h0, l0, h1, l1;
        bf16_split_pair(v.x, v.y, h0, l0);
        bf16_split_pair(v.z, v.w, h1, l1);
        size_t o = (size_t)row * 128 + (kk >> 1);
        *(uint2*)(g_wh + o) = make_uint2(h0, h1);
        *(uint2*)(g_wl + o) = make_uint2(l0, l1);
    }
}

// ========== fused: interleaved scatter + bf16 split GEMM =================
// bid < 1250: odd -> scatter (bid>>1), even -> GEMM (bid>>1)
// bid >= 1250: GEMM (bid - 625)
// GEMM: xw blocks 2-term (Ah*Bh + Al*Bh), xr blocks 3-term (+ Ah*Bl).
#define SCAT_B 625
#define GEMM_BX 157

#define KC 32
#define KS 2
#define A_FRAG_U32 (8 * KS * 32 * 4)
#define B_FRAG_U32 (16 * KS * 32 * 2)

struct SmemGemm {
    uint32_t AH[A_FRAG_U32];
    uint32_t AL[A_FRAG_U32];
    uint32_t BH[B_FRAG_U32];
    uint32_t BL[B_FRAG_U32];
};

#define MMA_BF16(d, a, b) \
    asm volatile("mma.sync.aligned.m16n8k16.row.col.f32.bf16.bf16.f32 " \
                 "{%0,%1,%2,%3}, {%4,%5,%6,%7}, {%8,%9}, {%0,%1,%2,%3};" \
                 : "+f"((d)[0]), "+f"((d)[1]), "+f"((d)[2]), "+f"((d)[3]) \
                 : "r"((a).x), "r"((a).y), "r"((a).z), "r"((a).w), \
                   "r"((b).x), "r"((b).y))

__global__ __launch_bounds__(256, 2) void gemm_scat_kernel(
    const int* __restrict__ ei, const float* __restrict__ b1)
{
    __shared__ SmemGemm sm;
    const int bid = blockIdx.x;
    const int tid = threadIdx.x;

    if (bid < 2 * SCAT_B && (bid & 1)) {
        // ---------------- scatter path ----------------
        int e8 = ((bid >> 1) * 256 + tid) * 8;
        #pragma unroll
        for (int h = 0; h < 2; h++) {
            int4 s = *(const int4*)(ei + e8 + h * 4);
            int4 d = *(const int4*)(ei + EE + e8 + h * 4);
            int d0 = clampN(d.x), d1 = clampN(d.y), d2 = clampN(d.z), d3 = clampN(d.w);
            int p0 = atomicAdd(&g_cnt[d0], 1);
            int p1 = atomicAdd(&g_cnt[d1], 1);
            int p2 = atomicAdd(&g_cnt[d2], 1);
            int p3 = atomicAdd(&g_cnt[d3], 1);
            if (p0 < STR) g_bucket[(size_t)d0 * STR + p0] = clampN(s.x);
            if (p1 < STR) g_bucket[(size_t)d1 * STR + p1] = clampN(s.y);
            if (p2 < STR) g_bucket[(size_t)d2 * STR + p2] = clampN(s.z);
            if (p3 < STR) g_bucket[(size_t)d3 * STR + p3] = clampN(s.w);
        }
        return;
    }

    // ---------------- GEMM path ----------------
    const int g = (bid < 2 * SCAT_B) ? (bid >> 1) : (bid - SCAT_B);
    const int m0 = (g % GEMM_BX) * 128;
    const int j0 = (g / GEMM_BX) * 128;
    const bool to_xw = (j0 < 256);

    const int wid = tid >> 5;
    const int lane = tid & 31;
    const int wr = wid >> 1;
    const int wc = wid & 1;

    const int prow = tid >> 1;
    const int phalf = tid & 1;
    const int rr = prow & 15;
    const int msub = prow >> 4;
    const int nsub = prow >> 3;
    const int nn = prow & 7;

    const int garow = m0 + prow;
    const bool avalid = (garow < NN);
    const uint4* xh4 = (const uint4*)(g_xh + (size_t)min(garow, NN - 1) * 128);
    const uint4* xl4 = (const uint4*)(g_xl + (size_t)min(garow, NN - 1) * 128);
    const uint4* wh4 = (const uint4*)(g_wh + (size_t)(j0 + prow) * 128);
    const uint4* wl4 = (const uint4*)(g_wl + (size_t)(j0 + prow) * 128);

    float acc[2][8][4];
    #pragma unroll
    for (int mi = 0; mi < 2; mi++)
        #pragma unroll
        for (int ni = 0; ni < 8; ni++)
            #pragma unroll
            for (int q = 0; q < 4; q++) acc[mi][ni][q] = 0.f;

    for (int kc = 0; kc < CC / KC; kc++) {
        {
            int u = kc * 4 + phalf * 2;
            uint4 ah0 = xh4[u], ah1 = xh4[u + 1];
            uint4 al0 = xl4[u], al1 = xl4[u + 1];
            if (!avalid) { ah0 = ah1 = al0 = al1 = make_uint4(0, 0, 0, 0); }
            uint4 bh0 = wh4[u], bh1 = wh4[u + 1];
            #pragma unroll
            for (int q = 0; q < 8; q++) {
                uint32_t ah = (q < 4) ? ((const uint32_t*)&ah0)[q] : ((const uint32_t*)&ah1)[q - 4];
                uint32_t al = (q < 4) ? ((const uint32_t*)&al0)[q] : ((const uint32_t*)&al1)[q - 4];
                uint32_t bh = (q < 4) ? ((const uint32_t*)&bh0)[q] : ((const uint32_t*)&bh1)[q - 4];
                int alane = (rr & 7) * 4 + (q & 3);
                int aslot = (rr >> 3) + ((q >> 2) << 1);
                int aoff = (((msub * KS + phalf) * 32 + alane) << 2) + aslot;
                sm.AH[aoff] = ah; sm.AL[aoff] = al;
                int blane = nn * 4 + (q & 3);
                int bslot = q >> 2;
                int boff = (((nsub * KS + phalf) * 32 + blane) << 1) + bslot;
                sm.BH[boff] = bh;
            }
            if (!to_xw) {
                uint4 bl0 = wl4[u], bl1 = wl4[u + 1];
                #pragma unroll
                for (int q = 0; q < 8; q++) {
                    uint32_t bl = (q < 4) ? ((const uint32_t*)&bl0)[q] : ((const uint32_t*)&bl1)[q - 4];
                    int blane = nn * 4 + (q & 3);
                    int bslot = q >> 2;
                    int boff = (((nsub * KS + phalf) * 32 + blane) << 1) + bslot;
                    sm.BL[boff] = bl;
                }
            }
        }
        __syncthreads();
        #pragma unroll
        for (int ks = 0; ks < KS; ks++) {
            uint4 Ah[2], Al[2];
            #pragma unroll
            for (int mi = 0; mi < 2; mi++) {
                int ms = wr * 2 + mi;
                int off = ((ms * KS + ks) * 32 + lane) << 2;
                Ah[mi] = *(const uint4*)&sm.AH[off];
                Al[mi] = *(const uint4*)&sm.AL[off];
            }
            #pragma unroll
            for (int ni = 0; ni < 8; ni++) {
                int ns = wc * 8 + ni;
                int boff = ((ns * KS + ks) * 32 + lane) << 1;
                uint2 Bh = *(const uint2*)&sm.BH[boff];
                #pragma unroll
                for (int mi = 0; mi < 2; mi++) {
                    MMA_BF16(acc[mi][ni], Ah[mi], Bh);
                    MMA_BF16(acc[mi][ni], Al[mi], Bh);
                }
                if (!to_xw) {
                    uint2 Bl = *(const uint2*)&sm.BL[boff];
                    #pragma unroll
                    for (int mi = 0; mi < 2; mi++)
                        MMA_BF16(acc[mi][ni], Ah[mi], Bl);
                }
            }
        }
        __syncthreads();
    }

    #pragma unroll
    for (int mi = 0; mi < 2; mi++) {
        int r0 = m0 + wr * 32 + mi * 16 + (lane >> 2);
        #pragma unroll
        for (int ni = 0; ni < 8; ni++) {
            int col = j0 + wc * 64 + ni * 8 + (lane & 3) * 2;
            if (to_xw) {
                if (r0 < NN)
                    g_xwh[(size_t)r0 * 128 + (col >> 1)] = pack_bf16x2(acc[mi][ni][0], acc[mi][ni][1]);
                if (r0 + 8 < NN)
                    g_xwh[(size_t)(r0 + 8) * 128 + (col >> 1)] = pack_bf16x2(acc[mi][ni][2], acc[mi][ni][3]);
            } else {
                int jj = col - 256;
                float2 bv = *(const float2*)(b1 + jj);
                if (r0 < NN)
                    *(float2*)(g_xr + (size_t)r0 * CC + jj) =
                        make_float2(acc[mi][ni][0] + bv.x, acc[mi][ni][1] + bv.y);
                if (r0 + 8 < NN)
                    *(float2*)(g_xr + (size_t)(r0 + 8) * CC + jj) =
                        make_float2(acc[mi][ni][2] + bv.x, acc[mi][ni][3] + bv.y);
            }
        }
    }
}

// ---- fused: bf16 bucket gather (depth-2 HADD2 tree) + epilogue + proj ---
__device__ __forceinline__ void accum8(float* a, uint4 q) {
    a[0] += __uint_as_float(q.x << 16);
    a[1] += __uint_as_float(q.x & 0xFFFF0000u);
    a[2] += __uint_as_float(q.y << 16);
    a[3] += __uint_as_float(q.y & 0xFFFF0000u);
    a[4] += __uint_as_float(q.z << 16);
    a[5] += __uint_as_float(q.z & 0xFFFF0000u);
    a[6] += __uint_as_float(q.w << 16);
    a[7] += __uint_as_float(q.w & 0xFFFF0000u);
}
__device__ __forceinline__ uint4 hadd2u4(uint4 a, uint4 b) {
    return make_uint4(hadd2u(a.x, b.x), hadd2u(a.y, b.y),
                      hadd2u(a.z, b.z), hadd2u(a.w, b.w));
}

__global__ __launch_bounds__(128) void agg_st_kernel(const float* __restrict__ W2l,
                                                     const float* __restrict__ W2r)
{
    int n = (int)((blockIdx.x * 128 + threadIdx.x) >> 5);
    int lane = threadIdx.x & 31;
    if (n >= NN) return;
    const int* lst = g_bucket + (size_t)n * STR;
    int cnt = g_cnt[n];
    int m = min(cnt, STR);

    const uint4* base = (const uint4*)g_xwh;   // row = 32 uint4
    float a[8] = {};

    int i = 0;
    for (; i + 4 <= m; i += 4) {
        int4 s4 = *(const int4*)(lst + i);
        uint4 q0 = base[(size_t)s4.x * 32 + lane];
        uint4 q1 = base[(size_t)s4.y * 32 + lane];
        uint4 q2 = base[(size_t)s4.z * 32 + lane];
        uint4 q3 = base[(size_t)s4.w * 32 + lane];
        accum8(a, hadd2u4(hadd2u4(q0, q1), hadd2u4(q2, q3)));   // depth-2 bf16 tree
    }
    if (i + 2 <= m) {
        uint4 q0 = base[(size_t)lst[i] * 32 + lane];
        uint4 q1 = base[(size_t)lst[i + 1] * 32 + lane];
        accum8(a, hadd2u4(q0, q1));
        i += 2;
    }
    if (i < m) {
        accum8(a, base[(size_t)lst[i] * 32 + lane]);
    }

    float inv = 1.0f / fmaxf((float)cnt, 1.0f);
    float su = 0.f, tv = 0.f;
    {
        int c0 = lane * 8;
        float4 R = *(const float4*)(g_xr + (size_t)n * CC + c0);
        float4 U = __ldg((const float4*)(W2l + c0));
        float4 V = __ldg((const float4*)(W2r + c0));
        float h;
        h = fmaxf(fmaf(inv, a[0], R.x), 0.f); su = fmaf(h, U.x, su); tv = fmaf(h, V.x, tv);
        h = fmaxf(fmaf(inv, a[1], R.y), 0.f); su = fmaf(h, U.y, su); tv = fmaf(h, V.y, tv);
        h = fmaxf(fmaf(inv, a[2], R.z), 0.f); su = fmaf(h, U.z, su); tv = fmaf(h, V.z, tv);
        h = fmaxf(fmaf(inv, a[3], R.w), 0.f); su = fmaf(h, U.w, su); tv = fmaf(h, V.w, tv);
        R = *(const float4*)(g_xr + (size_t)n * CC + c0 + 4);
        U = __ldg((const float4*)(W2l + c0 + 4));
        V = __ldg((const float4*)(W2r + c0 + 4));
        h = fmaxf(fmaf(inv, a[4], R.x), 0.f); su = fmaf(h, U.x, su); tv = fmaf(h, V.x, tv);
        h = fmaxf(fmaf(inv, a[5], R.y), 0.f); su = fmaf(h, U.y, su); tv = fmaf(h, V.y, tv);
        h = fmaxf(fmaf(inv, a[6], R.z), 0.f); su = fmaf(h, U.z, su); tv = fmaf(h, V.z, tv);
        h = fmaxf(fmaf(inv, a[7], R.w), 0.f); su = fmaf(h, U.w, su); tv = fmaf(h, V.w, tv);
    }
    #pragma unroll
    for (int o = 16; o > 0; o >>= 1) {
        su += __shfl_down_sync(0xffffffffu, su, o);
        tv += __shfl_down_sync(0xffffffffu, tv, o);
    }
    if (lane == 0) { g_s[n] = su; g_t[n] = tv; }
}

// ---- fused: layer-2 scalar gather + relu + fc dot (warp per node) -------
__global__ __launch_bounds__(256) void l2final_kernel(const float* __restrict__ fcw,
                                                      const float* __restrict__ b2)
{
    __shared__ float ws[8];
    int tid = threadIdx.x;
    int wid = tid >> 5;
    int lane = tid & 31;
    int n = (int)((blockIdx.x * 256 + tid) >> 5);
    float local = 0.f;
    if (n < NN) {
        const int* lst = g_bucket + (size_t)n * STR;
        int cnt = g_cnt[n];
        int m = min(cnt, STR);
        float sum = 0.f;
        for (int i = lane; i < m; i += 32) sum += g_s[lst[i]];
        #pragma unroll
        for (int o = 16; o > 0; o >>= 1)
            sum += __shfl_down_sync(0xffffffffu, sum, o);
        if (lane == 0) {
            float inv = 1.0f / fmaxf((float)cnt, 1.0f);
            float h = fmaxf(fmaf(inv, sum, b2[0] + g_t[n]), 0.f);
            local = h * fcw[n];
        }
    }
    if (lane == 0) ws[wid] = local;
    __syncthreads();
    if (tid == 0) {
        float s = ws[0] + ws[1] + ws[2] + ws[3] + ws[4] + ws[5] + ws[6] + ws[7];
        g_part[blockIdx.x] = s;
    }
}

#define L2_B 2500

__global__ __launch_bounds__(1024) void final2_kernel(float* __restrict__ out,
                                                      const float* __restrict__ fcb)
{
    __shared__ float sdata[1024];
    int tid = threadIdx.x;
    float v = 0.f;
    for (int i = tid; i < L2_B; i += 1024) v += g_part[i];
    sdata[tid] = v;
    __syncthreads();
    for (int s = 512; s > 0; s >>= 1) {
        if (tid < s) sdata[tid] += sdata[tid + s];
        __syncthreads();
    }
    if (tid == 0) out[0] = sdata[0] + fcb[0];
}

// ---------------- launch ----------------
extern "C" void kernel_launch(void* const* d_in, const int* in_sizes, int n_in,
                              void* d_out, int out_size) {
    const float* x    = (const float*)d_in[0];
    const int*   ei   = (const int*)d_in[1];     // int32 (JAX x64 disabled)
    const float* W1l  = (const float*)d_in[2];
    const float* b1   = (const float*)d_in[3];
    const float* W1r  = (const float*)d_in[4];
    const float* W2l  = (const float*)d_in[5];
    const float* b2   = (const float*)d_in[6];
    const float* W2r  = (const float*)d_in[7];
    const float* fcw  = (const float*)d_in[8];
    const float* fcb  = (const float*)d_in[9];
    float* out = (float*)d_out;

    prep_kernel<<<ZB + XC_B + WC_B, 256>>>(x, W1l, W1r);

    gemm_scat_kernel<<<2 * SCAT_B + 3, 256>>>(ei, b1);

    agg_st_kernel<<<(NN * 32 + 127) / 128, 128>>>(W2l, W2r);

    l2final_kernel<<<L2_B, 256>>>(fcw, b2);
    final2_kernel<<<1, 1024>>>(out, fcb);
}